// round 9
// baseline (speedup 1.0000x reference)
#include <cuda_runtime.h>
#include <cstdint>

#define BSZ 16
#define TOK 784
#define CH  768
#define NCLS 200
#define LDL 192          // logits row stride (main cols only; tail fused later)

// ---------------- scratch (device globals; no allocations allowed) ----------
__device__ float g_logits[BSZ * TOK * LDL];    // 9.6 MB
__device__ float g_mlog[BSZ * TOK];
__device__ int   g_sel[BSZ];
__device__ float g_ym[576 * 192];              // (b,6x6) @ W_m^T + b_m
__device__ float g_ys[256 * 384];              // (b,4x4) @ W_s^T + b_s

// ============ big-M GEMM: 128x64 tile, 8x4 per thread, double-buffered =====
// C[m, n_global] = sum_k A[m,k] * W[n,k] + bias[n]
// Requires: M % 128 == 0, K % 16 == 0, all 64 N-columns valid.
__global__ __launch_bounds__(256) void gemm_nt128(
    const float* __restrict__ A, const float* __restrict__ W,
    const float* __restrict__ bias, float* __restrict__ Cout,
    int K, int ldc)
{
    __shared__ float As[2][16][128];
    __shared__ float Bs[2][16][64];
    const int tid = threadIdx.x;
    const int bm = blockIdx.y * 128;
    const int bn = blockIdx.x * 64;
    const int tx = tid & 15;   // n-dir: 4 cols each
    const int ty = tid >> 4;   // m-dir: 8 rows each

    float acc[8][4];
#pragma unroll
    for (int i = 0; i < 8; i++)
#pragma unroll
        for (int j = 0; j < 4; j++) acc[i][j] = 0.f;

    const int alr = tid >> 1;             // A-loader row 0..127
    const int alc = (tid & 1) << 3;       // A-loader col 0 or 8
    const float* Aptr = A + (size_t)(bm + alr) * K + alc;
    const int blr = tid >> 2;             // B-loader row 0..63
    const int blc = (tid & 3) << 2;       // B-loader col 0,4,8,12
    const float* Wptr = W + (size_t)(bn + blr) * K + blc;

    // ---- preload chunk 0 into buffer 0 ----
    {
        float4 a0 = *(const float4*)(Aptr);
        float4 a1 = *(const float4*)(Aptr + 4);
        float4 bv = *(const float4*)(Wptr);
        As[0][alc + 0][alr] = a0.x; As[0][alc + 1][alr] = a0.y;
        As[0][alc + 2][alr] = a0.z; As[0][alc + 3][alr] = a0.w;
        As[0][alc + 4][alr] = a1.x; As[0][alc + 5][alr] = a1.y;
        As[0][alc + 6][alr] = a1.z; As[0][alc + 7][alr] = a1.w;
        Bs[0][blc + 0][blr] = bv.x; Bs[0][blc + 1][blr] = bv.y;
        Bs[0][blc + 2][blr] = bv.z; Bs[0][blc + 3][blr] = bv.w;
    }
    __syncthreads();

    const int NIT = K >> 4;               // 48 for K=768
    for (int it = 0; it < NIT; it++) {
        const int cur = it & 1;
        const bool more = (it + 1 < NIT);
        float4 na0, na1, nbv;
        if (more) {                       // prefetch next chunk (LDG overlaps FFMAs)
            int k0 = (it + 1) << 4;
            na0 = *(const float4*)(Aptr + k0);
            na1 = *(const float4*)(Aptr + k0 + 4);
            nbv = *(const float4*)(Wptr + k0);
        }
#pragma unroll
        for (int k = 0; k < 16; k++) {
            float4 am0 = *(const float4*)&As[cur][k][ty << 3];
            float4 am1 = *(const float4*)&As[cur][k][(ty << 3) + 4];
            float4 b   = *(const float4*)&Bs[cur][k][tx << 2];
            acc[0][0] += am0.x * b.x; acc[0][1] += am0.x * b.y;
            acc[0][2] += am0.x * b.z; acc[0][3] += am0.x * b.w;
            acc[1][0] += am0.y * b.x; acc[1][1] += am0.y * b.y;
            acc[1][2] += am0.y * b.z; acc[1][3] += am0.y * b.w;
            acc[2][0] += am0.z * b.x; acc[2][1] += am0.z * b.y;
            acc[2][2] += am0.z * b.z; acc[2][3] += am0.z * b.w;
            acc[3][0] += am0.w * b.x; acc[3][1] += am0.w * b.y;
            acc[3][2] += am0.w * b.z; acc[3][3] += am0.w * b.w;
            acc[4][0] += am1.x * b.x; acc[4][1] += am1.x * b.y;
            acc[4][2] += am1.x * b.z; acc[4][3] += am1.x * b.w;
            acc[5][0] += am1.y * b.x; acc[5][1] += am1.y * b.y;
            acc[5][2] += am1.y * b.z; acc[5][3] += am1.y * b.w;
            acc[6][0] += am1.z * b.x; acc[6][1] += am1.z * b.y;
            acc[6][2] += am1.z * b.z; acc[6][3] += am1.z * b.w;
            acc[7][0] += am1.w * b.x; acc[7][1] += am1.w * b.y;
            acc[7][2] += am1.w * b.z; acc[7][3] += am1.w * b.w;
        }
        if (more) {
            const int nxt = cur ^ 1;      // safe: barrier at end of it-1 drained reads
            As[nxt][alc + 0][alr] = na0.x; As[nxt][alc + 1][alr] = na0.y;
            As[nxt][alc + 2][alr] = na0.z; As[nxt][alc + 3][alr] = na0.w;
            As[nxt][alc + 4][alr] = na1.x; As[nxt][alc + 5][alr] = na1.y;
            As[nxt][alc + 6][alr] = na1.z; As[nxt][alc + 7][alr] = na1.w;
            Bs[nxt][blc + 0][blr] = nbv.x; Bs[nxt][blc + 1][blr] = nbv.y;
            Bs[nxt][blc + 2][blr] = nbv.z; Bs[nxt][blc + 3][blr] = nbv.w;
            __syncthreads();
        }
    }

    // vectorized epilogue: one STG.128 per output row-group
    const float4 b4 = *(const float4*)(bias + bn + (tx << 2));
#pragma unroll
    for (int i = 0; i < 8; i++) {
        int m = bm + (ty << 3) + i;
        float4 v = make_float4(acc[i][0] + b4.x, acc[i][1] + b4.y,
                               acc[i][2] + b4.z, acc[i][3] + b4.w);
        *(float4*)(Cout + (size_t)m * ldc + bn + (tx << 2)) = v;
    }
}

// ===== fused: fc tail cols [192,200) + per-token max(softmax) ==============
// One warp per token. Tail logits computed in-register; main 192 logits read
// from g_logits; writes g_mlog[t] = 1/sum(exp(l - lmax)).
__global__ __launch_bounds__(256) void softmax_tail_kernel(
    const float* __restrict__ x, const float* __restrict__ W_fc,
    const float* __restrict__ b_fc)
{
    __shared__ float Ws[8 * CH];     // W_fc rows 192..199, 24 KB
    __shared__ float bs[8];
    const int tid = threadIdx.x;
    // stage tail W (1536 float4 by 256 threads x 6)
#pragma unroll
    for (int i = 0; i < 6; i++) {
        int idx = i * 256 + tid;                     // 0..1535
        ((float4*)Ws)[idx] = *(const float4*)(W_fc + (size_t)192 * CH + idx * 4);
    }
    if (tid < 8) bs[tid] = b_fc[192 + tid];
    __syncthreads();

    const int warp = tid >> 5, lane = tid & 31;
    const int t = blockIdx.x * 8 + warp;             // token, grid covers 12544
    const float4* xr = (const float4*)(x + (size_t)t * CH);

    // lane owns k4 = lane + 32*i, i<6  (covers all 192 float4 = 768 k)
    float4 xv[6];
#pragma unroll
    for (int i = 0; i < 6; i++) xv[i] = xr[lane + 32 * i];

    float tail[8];
#pragma unroll
    for (int n = 0; n < 8; n++) {
        const float4* wr = (const float4*)(Ws + n * CH);
        float s = 0.f;
#pragma unroll
        for (int i = 0; i < 6; i++) {
            float4 w = wr[lane + 32 * i];
            s += xv[i].x * w.x + xv[i].y * w.y + xv[i].z * w.z + xv[i].w * w.w;
        }
#pragma unroll
        for (int o = 16; o; o >>= 1) s += __shfl_xor_sync(0xffffffffu, s, o);
        tail[n] = s + bs[n];                         // full value on all lanes
    }

    // main 192 logits: 6 per lane
    const float* row = g_logits + (size_t)t * LDL;
    float lv[6];
#pragma unroll
    for (int i = 0; i < 6; i++) lv[i] = row[lane + 32 * i];

    float m = -1e30f;
#pragma unroll
    for (int i = 0; i < 6; i++) m = fmaxf(m, lv[i]);
#pragma unroll
    for (int n = 0; n < 8; n++) m = fmaxf(m, tail[n]);
#pragma unroll
    for (int o = 16; o; o >>= 1) m = fmaxf(m, __shfl_xor_sync(0xffffffffu, m, o));

    float s = 0.f;
#pragma unroll
    for (int i = 0; i < 6; i++) s += __expf(lv[i] - m);
    if (lane < 8) s += __expf(tail[lane] - m);       // tail added exactly once
#pragma unroll
    for (int o = 16; o; o >>= 1) s += __shfl_xor_sync(0xffffffffu, s, o);
    if (lane == 0) g_mlog[t] = 1.0f / s;
}

// ------- window-mean (8x8, stride 3, pad 2) * mask -> argmax over 81 --------
__global__ void select_kernel(const float* __restrict__ mask)
{
    __shared__ float vals[81];
    int b = blockIdx.x;
    int p = threadIdx.x;
    if (p < 81) {
        int pr = p / 9, pc = p % 9;
        float s = 0.f;
        for (int ki = 0; ki < 8; ki++) {
            int fi = pr * 3 + ki - 2;
            if (fi < 0 || fi >= 28) continue;
            for (int kj = 0; kj < 8; kj++) {
                int fj = pc * 3 + kj - 2;
                if (fj < 0 || fj >= 28) continue;
                s += g_mlog[b * TOK + fi * 28 + fj];
            }
        }
        vals[p] = (s * (1.0f / 64.0f)) * mask[b * 81 + p];
    }
    __syncthreads();
    if (p == 0) {
        float best = vals[0]; int bi = 0;
        for (int i = 1; i < 81; i++)
            if (vals[i] > best) { best = vals[i]; bi = i; }
        g_sel[b] = bi;
    }
}

// ===== fused parts GEMM: gathers A-rows from x on the fly ==================
// 99 blocks in one wave:
//   bid [0,48):  part1 = Z_l(1024 rows) @ W_l^T + b_l -> out cols [0,192)
//   bid [48,75): Y_m   = Z_m(576 rows)  @ W_m^T + b_m -> g_ym
//   bid [75,99): Y_s   = Z_s(256 rows)  @ W_s^T + b_s -> g_ys
__global__ __launch_bounds__(256) void fused_parts_gemm(
    const float* __restrict__ x,
    const float* __restrict__ W_l, const float* __restrict__ b_l,
    const float* __restrict__ W_m, const float* __restrict__ b_m,
    const float* __restrict__ W_s, const float* __restrict__ b_s,
    float* __restrict__ out)
{
    __shared__ float As[16][64];
    __shared__ float Bs[16][64];
    const int tid = threadIdx.x;
    const int bid = blockIdx.x;

    int seg, bm, bn;
    const float *W, *bias;
    if (bid < 48)      { seg = 0; bn = bid % 3;  bm = bid / 3;  W = W_l; bias = b_l; }
    else if (bid < 75) { seg = 1; int t = bid - 48; bn = t % 3; bm = t / 3; W = W_m; bias = b_m; }
    else               { seg = 2; int t = bid - 75; bn = t % 6; bm = t / 6; W = W_s; bias = b_s; }

    const int lr = tid >> 2;          // loader row 0..63
    const int lc = (tid & 3) << 2;    // loader col 0,4,8,12

    // --- per-row source mapping (computed once) ---
    int gr = bm * 64 + lr;
    int b, y, xx;
    if (seg == 0)      { b = gr >> 6; int i = gr & 63;  y = i >> 3;        xx = i & 7; }
    else if (seg == 1) { b = gr / 36; int i = gr % 36;  y = i / 6 + 1;     xx = i % 6 + 1; }
    else               { b = gr / 16; int i = gr % 16;  y = (i >> 2) + 2;  xx = (i & 3) + 2; }
    int p = g_sel[b];
    int fi = (p / 9) * 3 + y - 2;
    int fj = (p % 9) * 3 + xx - 2;
    const bool avalid = (fi >= 0 && fi < 28 && fj >= 0 && fj < 28);
    const float* Aptr = x + (avalid ? ((size_t)(b * TOK + fi * 28 + fj)) * CH : 0) + lc;
    const float* Wptr = W + (size_t)(bn * 64 + lr) * CH + lc;

    const int tx = tid & 15;
    const int ty = tid >> 4;
    float acc[4][4];
#pragma unroll
    for (int i = 0; i < 4; i++)
#pragma unroll
        for (int j = 0; j < 4; j++) acc[i][j] = 0.f;

    for (int k0 = 0; k0 < CH; k0 += 16) {
        float4 av = make_float4(0.f, 0.f, 0.f, 0.f);
        if (avalid) av = *(const float4*)(Aptr + k0);
        float4 bv = *(const float4*)(Wptr + k0);
        As[lc + 0][lr] = av.x; As[lc + 1][lr] = av.y;
        As[lc + 2][lr] = av.z; As[lc + 3][lr] = av.w;
        Bs[lc + 0][lr] = bv.x; Bs[lc + 1][lr] = bv.y;
        Bs[lc + 2][lr] = bv.z; Bs[lc + 3][lr] = bv.w;
        __syncthreads();
#pragma unroll
        for (int k = 0; k < 16; k++) {
            float4 a = *(const float4*)&As[k][ty << 2];
            float4 bb = *(const float4*)&Bs[k][tx << 2];
            acc[0][0] += a.x * bb.x; acc[0][1] += a.x * bb.y;
            acc[0][2] += a.x * bb.z; acc[0][3] += a.x * bb.w;
            acc[1][0] += a.y * bb.x; acc[1][1] += a.y * bb.y;
            acc[1][2] += a.y * bb.z; acc[1][3] += a.y * bb.w;
            acc[2][0] += a.z * bb.x; acc[2][1] += a.z * bb.y;
            acc[2][2] += a.z * bb.z; acc[2][3] += a.z * bb.w;
            acc[3][0] += a.w * bb.x; acc[3][1] += a.w * bb.y;
            acc[3][2] += a.w * bb.z; acc[3][3] += a.w * bb.w;
        }
        __syncthreads();
    }

    // vectorized epilogue: one STG.128 per output row
    const int nbase = bn * 64 + (tx << 2);
    const float4 b4 = *(const float4*)(bias + nbase);
#pragma unroll
    for (int i = 0; i < 4; i++) {
        int m = bm * 64 + (ty << 2) + i;
        float4 v = make_float4(acc[i][0] + b4.x, acc[i][1] + b4.y,
                               acc[i][2] + b4.z, acc[i][3] + b4.w);
        if (seg == 0)      *(float4*)(out + (size_t)m * CH + nbase) = v;
        else if (seg == 1) *(float4*)(g_ym + m * 192 + nbase) = v;
        else               *(float4*)(g_ys + m * 384 + nbase) = v;
    }
}

// ===== bilinear upsample Y_m (6x6) and Y_s (4x4) into ff_cat cols ==========
__global__ void interp_ms_kernel(float* __restrict__ out)
{
    int pos = blockIdx.x;   // 0..63
    int b   = blockIdx.y;   // 0..15
    int tid = threadIdx.x;  // 0..383
    int y = pos >> 3, xo = pos & 7;
    float* orow = out + (size_t)(b * 64 + pos) * CH;

    if (tid < 192) {       // m: 6x6 -> 8x8, cols [192,384)
        float sy = fminf(fmaxf(y * 0.75f - 0.125f, 0.f), 5.f);
        float sx = fminf(fmaxf(xo * 0.75f - 0.125f, 0.f), 5.f);
        int y0 = (int)sy; float fy = sy - (float)y0; int y1 = min(y0 + 1, 5);
        int x0 = (int)sx; float fx = sx - (float)x0; int x1 = min(x0 + 1, 5);
        const float* Y = g_ym + (size_t)b * 36 * 192 + tid;
        float v00 = Y[(y0 * 6 + x0) * 192], v01 = Y[(y0 * 6 + x1) * 192];
        float v10 = Y[(y1 * 6 + x0) * 192], v11 = Y[(y1 * 6 + x1) * 192];
        orow[192 + tid] = (1.f - fy) * ((1.f - fx) * v00 + fx * v01)
                        + fy * ((1.f - fx) * v10 + fx * v11);
    }
    {                      // s: 4x4 -> 8x8, cols [384,768)
        float sy = fminf(fmaxf(y * 0.5f - 0.25f, 0.f), 3.f);
        float sx = fminf(fmaxf(xo * 0.5f - 0.25f, 0.f), 3.f);
        int y0 = (int)sy; float fy = sy - (float)y0; int y1 = min(y0 + 1, 3);
        int x0 = (int)sx; float fx = sx - (float)x0; int x1 = min(x0 + 1, 3);
        const float* Y = g_ys + (size_t)b * 16 * 384 + tid;
        float v00 = Y[(y0 * 4 + x0) * 384], v01 = Y[(y0 * 4 + x1) * 384];
        float v10 = Y[(y1 * 4 + x0) * 384], v11 = Y[(y1 * 4 + x1) * 384];
        orow[384 + tid] = (1.f - fy) * ((1.f - fx) * v00 + fx * v01)
                        + fy * ((1.f - fx) * v10 + fx * v11);
    }
}

// image_part: selected 128x128 patch (pad 32 over 448x448) resized to 224x224
__global__ void image_resize_kernel(const float* __restrict__ img,
                                    float* __restrict__ out)
{
    int idx = blockIdx.x * blockDim.x + threadIdx.x;
    const int TOTAL = BSZ * 3 * 224 * 224;
    if (idx >= TOTAL) return;
    int xo = idx % 224;
    int y  = (idx / 224) % 224;
    int ch = (idx / (224 * 224)) % 3;
    int b  = idx / (224 * 224 * 3);
    int p = g_sel[b]; int pr = p / 9, pc = p % 9;

    const float S = 4.0f / 7.0f;  // 128/224
    float sy = fminf(fmaxf((y + 0.5f) * S - 0.5f, 0.f), 127.f);
    float sx = fminf(fmaxf((xo + 0.5f) * S - 0.5f, 0.f), 127.f);
    int y0 = (int)sy; float fy = sy - (float)y0; int y1 = min(y0 + 1, 127);
    int x0 = (int)sx; float fx = sx - (float)x0; int x1 = min(x0 + 1, 127);

    const float* ib = img + ((size_t)b * 3 + ch) * 448 * 448;
    int gy0 = pr * 48 + y0 - 32, gy1 = pr * 48 + y1 - 32;
    int gx0 = pc * 48 + x0 - 32, gx1 = pc * 48 + x1 - 32;
    bool vy0 = (gy0 >= 0 && gy0 < 448), vy1 = (gy1 >= 0 && gy1 < 448);
    bool vx0 = (gx0 >= 0 && gx0 < 448), vx1 = (gx1 >= 0 && gx1 < 448);
    float v00 = (vy0 && vx0) ? ib[gy0 * 448 + gx0] : 0.f;
    float v01 = (vy0 && vx1) ? ib[gy0 * 448 + gx1] : 0.f;
    float v10 = (vy1 && vx0) ? ib[gy1 * 448 + gx0] : 0.f;
    float v11 = (vy1 && vx1) ? ib[gy1 * 448 + gx1] : 0.f;
    float v = (1.f - fy) * ((1.f - fx) * v00 + fx * v01)
            + fy * ((1.f - fx) * v10 + fx * v11);
    out[idx] = v;
}

// ---------------------------------------------------------------------------
extern "C" void kernel_launch(void* const* d_in, const int* in_sizes, int n_in,
                              void* d_out, int out_size)
{
    const float* x    = (const float*)d_in[0];   // [16,784,768]
    const float* mask = (const float*)d_in[1];   // [16,81]
    const float* img  = (const float*)d_in[2];   // [16,3,448,448]
    const float* W_fc = (const float*)d_in[3];   // [200,768]
    const float* b_fc = (const float*)d_in[4];
    const float* W_l  = (const float*)d_in[5];   // [192,768]
    const float* b_l  = (const float*)d_in[6];
    const float* W_m  = (const float*)d_in[7];   // [192,768]
    const float* b_m  = (const float*)d_in[8];
    const float* W_s  = (const float*)d_in[9];   // [384,768]
    const float* b_s  = (const float*)d_in[10];
    float* out = (float*)d_out;

    static float* p_logits = nullptr;
    if (!p_logits) {
        cudaGetSymbolAddress((void**)&p_logits, g_logits);
    }

    // 1) logits cols [0,192) = x @ W_fc[0:192]^T + b_fc  (M=12544, K=768)
    gemm_nt128<<<dim3(3, 98), 256>>>(x, W_fc, b_fc, p_logits, CH, LDL);

    // 2) fused tail cols [192,200) + max-softmax per token
    softmax_tail_kernel<<<(BSZ * TOK) / 8, 256>>>(x, W_fc, b_fc);

    // 3) masked window-mean argmax -> sel[b]
    select_kernel<<<BSZ, 96>>>(mask);

    // 4) fused gather+GEMM for all three parts (one wave, 99 blocks)
    fused_parts_gemm<<<99, 256>>>(x, W_l, b_l, W_m, b_m, W_s, b_s, out);

    // 5) upsample m/s results into ff_cat cols [192,768)
    interp_ms_kernel<<<dim3(64, BSZ), 384>>>(out);

    // 6) image_part: selected image patch resized 128->224
    const int IMG_TOTAL = BSZ * 3 * 224 * 224;
    image_resize_kernel<<<(IMG_TOTAL + 255) / 256, 256>>>(
        img, out + (size_t)BSZ * 64 * CH);
}